// round 1
// baseline (speedup 1.0000x reference)
#include <cuda_runtime.h>
#include <cuda_bf16.h>

// LocallyConnected1d: out[b,c,o] = (1/8) * sum_{i<64,k<8} x[b,i,4o+k] * w[c,i,o,k]
// x: [128, 64, 1028] fp32, w: [1, 64, 64, 256, 8] fp32, out: [128, 64, 256] fp32

#define BB   128
#define CINC 64
#define COUT 64
#define OD   256
#define KW   8
#define STR  4
#define LL   1028
#define IC   8           // CIN chunk
#define RED  (IC * KW)   // 64 reduction rows per chunk

__device__ __forceinline__ void fma2(unsigned long long& acc,
                                     unsigned long long a,
                                     unsigned long long b) {
    asm("fma.rn.f32x2 %0, %1, %2, %0;" : "+l"(acc) : "l"(a), "l"(b));
}

__global__ __launch_bounds__(256, 2)
void lc1d_kernel(const float* __restrict__ x,
                 const float* __restrict__ w,
                 float* __restrict__ out) {
    __shared__ float Xs[RED][BB];    // 64 x 128 = 32 KB
    __shared__ float Ws[RED][COUT];  // 64 x 64  = 16 KB

    const int o   = blockIdx.x;
    const int tid = threadIdx.x;
    const int tb  = tid & 15;   // 16 groups along b
    const int tc  = tid >> 4;   // 16 groups along c
    const int c0  = tc * 4;

    // Per-thread tile: 4 b-pairs (b = 2*tb + 32*p + {0,1}) x 4 cout.
    // Pair base stride 32 across tb makes LDS.64 reads conflict-free.
    unsigned long long acc[4][4];
    #pragma unroll
    for (int c = 0; c < 4; c++)
        #pragma unroll
        for (int p = 0; p < 4; p++)
            acc[c][p] = 0ull;   // packed (0.0f, 0.0f)

    for (int ci = 0; ci < CINC / IC; ci++) {
        const int ibase = ci * IC;

        // ---- load X chunk: x[b, ibase+ii, 4o .. 4o+7] -> Xs[ii*8+k][b] ----
        #pragma unroll
        for (int it = 0; it < 4; it++) {
            int p  = tid + it * 256;     // 0..1023
            int b  = p & 127;
            int ii = p >> 7;
            const float4* src = reinterpret_cast<const float4*>(
                x + (size_t)(b * CINC + ibase + ii) * LL + o * STR);
            float4 v0 = src[0];
            float4 v1 = src[1];
            Xs[ii * KW + 0][b] = v0.x;  Xs[ii * KW + 1][b] = v0.y;
            Xs[ii * KW + 2][b] = v0.z;  Xs[ii * KW + 3][b] = v0.w;
            Xs[ii * KW + 4][b] = v1.x;  Xs[ii * KW + 5][b] = v1.y;
            Xs[ii * KW + 6][b] = v1.z;  Xs[ii * KW + 7][b] = v1.w;
        }

        // ---- load W chunk: w[c, ibase+ii, o, 0..7] -> Ws[ii*8+k][c] ----
        #pragma unroll
        for (int it = 0; it < 2; it++) {
            int q  = tid + it * 256;     // 0..511
            int c  = q & 63;
            int ii = q >> 6;
            const float4* src = reinterpret_cast<const float4*>(
                w + ((size_t)(c * CINC + ibase + ii) * OD + o) * KW);
            float4 v0 = src[0];
            float4 v1 = src[1];
            Ws[ii * KW + 0][c] = v0.x;  Ws[ii * KW + 1][c] = v0.y;
            Ws[ii * KW + 2][c] = v0.z;  Ws[ii * KW + 3][c] = v0.w;
            Ws[ii * KW + 4][c] = v1.x;  Ws[ii * KW + 5][c] = v1.y;
            Ws[ii * KW + 6][c] = v1.z;  Ws[ii * KW + 7][c] = v1.w;
        }

        __syncthreads();

        // ---- compute: 64 reduction rows, 16 packed FMAs each ----
        #pragma unroll 16
        for (int ik = 0; ik < RED; ik++) {
            unsigned long long xp[4];
            #pragma unroll
            for (int p = 0; p < 4; p++)
                xp[p] = *reinterpret_cast<const unsigned long long*>(
                    &Xs[ik][2 * tb + 32 * p]);

            float4 wv = *reinterpret_cast<const float4*>(&Ws[ik][c0]);
            float wf[4] = {wv.x, wv.y, wv.z, wv.w};

            #pragma unroll
            for (int c = 0; c < 4; c++) {
                unsigned long long wp;
                asm("mov.b64 %0, {%1, %1};" : "=l"(wp) : "f"(wf[c]));
                #pragma unroll
                for (int p = 0; p < 4; p++)
                    fma2(acc[c][p], xp[p], wp);
            }
        }

        __syncthreads();
    }

    // ---- epilogue: scale by 1/sqrt(64) = 0.125, scatter to out[b][c][o] ----
    const float scale = 0.125f;
    #pragma unroll
    for (int c = 0; c < 4; c++) {
        #pragma unroll
        for (int p = 0; p < 4; p++) {
            float lo, hi;
            asm("mov.b64 {%0, %1}, %2;" : "=f"(lo), "=f"(hi) : "l"(acc[c][p]));
            int b = 2 * tb + 32 * p;
            out[((size_t)b       * COUT + c0 + c) * OD + o] = lo * scale;
            out[((size_t)(b + 1) * COUT + c0 + c) * OD + o] = hi * scale;
        }
    }
}

extern "C" void kernel_launch(void* const* d_in, const int* in_sizes, int n_in,
                              void* d_out, int out_size) {
    const float* x = (const float*)d_in[0];
    const float* w = (const float*)d_in[1];
    float* out = (float*)d_out;
    lc1d_kernel<<<OD, 256>>>(x, w, out);
}